// round 1
// baseline (speedup 1.0000x reference)
#include <cuda_runtime.h>

// Problem constants
#define BB 8
#define NN 128
#define CC 64
#define INV_AVG (1.0f/49.0f)
#define NEG_SLOPE 0.01f

// ---------------- scratch (device globals; no allocation) ----------------
__device__ __align__(16) float g_CB[128*64];      // combined GEMM B matrix: k<64 -> C[op3][d][s], k>=64 -> C[op4][d][s]
__device__ __align__(16) float g_diag[BB*NN*CC];  // diag[b,t,d] = in[b,t,t,d]
__device__ __align__(16) float g_rsum[BB*NN*CC];  // rowsum/49
__device__ __align__(16) float g_csum[BB*NN*CC];  // colsum/49
__device__ float g_trace[BB*CC];                  // /49
__device__ float g_asum[BB*CC];                   // /49^2
__device__ __align__(16) float g_U [BB*NN*CC];    // i-indexed adds (+W+bias)
__device__ __align__(16) float g_V [BB*NN*CC];    // j-indexed adds
__device__ __align__(16) float g_Dg[BB*NN*CC];    // diagonal adds (+Wd+diag_bias)

// ---------------- P0: build combined coef matrix for the GEMM ----------------
__global__ void cb_kernel(const float* __restrict__ c00, const float* __restrict__ c01,
                          const float* __restrict__ c10, const float* __restrict__ c11) {
    int idx = blockIdx.x * blockDim.x + threadIdx.x;   // 8192 = 128*64
    if (idx >= 128*64) return;
    int s = idx & 63;
    int k = idx >> 6;
    int d = k & 63;
    int bop = (k < 64) ? 3 : 4;   // op3 = identity, op4 = transpose
    g_CB[idx] = c00[d*15 + bop] * c10[d*64 + s] + c01[s*15 + bop] * c11[d*64 + s];
}

// ---------------- P1: per-token stats ----------------
__global__ void stats_kernel(const float* __restrict__ in) {
    int bt = blockIdx.x;            // 0..1023
    int b = bt >> 7, t = bt & 127;
    int tid = threadIdx.x;          // 256
    int d  = tid & 63;
    int jl = tid >> 6;              // 0..3

    const float* rowbase = in + (size_t)((b*NN + t) * NN) * CC;   // in[b,t,j,d]
    float rs = 0.f;
    for (int j = jl; j < NN; j += 4) rs += rowbase[j*CC + d];

    const float* colbase = in + ((size_t)b*NN*NN + t) * CC;       // in[b,i,t,d]
    float cs = 0.f;
    for (int i = jl; i < NN; i += 4) cs += colbase[(size_t)i*NN*CC + d];

    __shared__ float red[2][4][64];
    red[0][jl][d] = rs;
    red[1][jl][d] = cs;
    __syncthreads();
    if (jl == 0) {
        float r = red[0][0][d] + red[0][1][d] + red[0][2][d] + red[0][3][d];
        float c = red[1][0][d] + red[1][1][d] + red[1][2][d] + red[1][3][d];
        int o = (b*NN + t)*CC + d;
        g_rsum[o] = r * INV_AVG;
        g_csum[o] = c * INV_AVG;
        g_diag[o] = rowbase[t*CC + d];
    }
}

// ---------------- P1b: trace / allsum ----------------
__global__ void trace_kernel() {
    int b = blockIdx.x;     // 8
    int d = threadIdx.x;    // 64
    float tr = 0.f, as = 0.f;
    for (int t = 0; t < NN; t++) {
        tr += g_diag[(b*NN + t)*CC + d];
        as += g_rsum[(b*NN + t)*CC + d];
    }
    g_trace[b*CC + d] = tr * INV_AVG;
    g_asum [b*CC + d] = as * INV_AVG;
}

// ---------------- P2: combine stats into U / V / Dg tables ----------------
// op mapping (0-based index into the 15-op basis):
//  Dg (diag-only): 0 (diag), 5 (rowsum), 6 (colsum);  + Wd: 7 (trace), 8 (allsum)
//  U  (i-indexed): 1 (diag), 9 (rowsum), 11 (colsum); + W:  13 (trace), 14 (allsum)
//  V  (j-indexed): 2 (diag), 10 (rowsum), 12 (colsum)
__global__ void combine_kernel(const float* __restrict__ c00, const float* __restrict__ c01,
                               const float* __restrict__ c10, const float* __restrict__ c11,
                               const float* __restrict__ bias, const float* __restrict__ dbias) {
    int blk = blockIdx.x;           // 64 = 8 b * 8 tgroups
    int b = blk >> 3, tg = blk & 7; // 16 tokens per group
    int tid = threadIdx.x;          // 256
    int s  = tid & 63;
    int tl = tid >> 6;              // 0..3 -> 4 tokens each

    __shared__ float sdiag[16][64], srsum[16][64], scsum[16][64];
    __shared__ float strace[64], sasum[64];

    int base = (b*NN + tg*16) * CC;
    for (int q = tid; q < 16*64; q += 256) {
        sdiag[q>>6][q&63] = g_diag[base + q];
        srsum[q>>6][q&63] = g_rsum[base + q];
        scsum[q>>6][q&63] = g_csum[base + q];
    }
    if (tid < 64) { strace[tid] = g_trace[b*CC + tid]; sasum[tid] = g_asum[b*CC + tid]; }
    __syncthreads();

    float c01b[15];
#pragma unroll
    for (int bb = 0; bb < 15; bb++) c01b[bb] = c01[s*15 + bb];

    float U[4] = {0,0,0,0}, V[4] = {0,0,0,0}, Dg[4] = {0,0,0,0};
    float W = 0.f, Wd = 0.f;

    for (int d = 0; d < 64; d++) {
        float f10 = c10[d*64 + s], f11 = c11[d*64 + s];
        float c00d[15];
#pragma unroll
        for (int bb = 0; bb < 15; bb++) c00d[bb] = c00[d*15 + bb];   // broadcast across threads
#define CF(bb) (c00d[bb]*f10 + c01b[bb]*f11)
        float C0 = CF(0),  C1 = CF(1),  C2 = CF(2);
        float C5 = CF(5),  C6 = CF(6),  C7 = CF(7),  C8 = CF(8);
        float C9 = CF(9),  C10v = CF(10), C11v = CF(11), C12v = CF(12);
        float C13 = CF(13), C14 = CF(14);
#undef CF
        float tr = strace[d], as = sasum[d];
        W  += tr*C13 + as*C14;
        Wd += tr*C7  + as*C8;
#pragma unroll
        for (int r = 0; r < 4; r++) {
            int t = tl*4 + r;
            float dg = sdiag[t][d], rsv = srsum[t][d], csv = scsum[t][d];
            U[r]  += dg*C1 + rsv*C9   + csv*C11v;
            V[r]  += dg*C2 + rsv*C10v + csv*C12v;
            Dg[r] += dg*C0 + rsv*C5   + csv*C6;
        }
    }

    float bs = bias[s], dbs = dbias[s];
#pragma unroll
    for (int r = 0; r < 4; r++) {
        int t = tl*4 + r;
        int o = (b*NN + tg*16 + t)*CC + s;
        g_U[o]  = U[r] + W + bs;
        g_V[o]  = V[r];
        g_Dg[o] = Dg[r] + Wd + dbs;
    }
}

// ---------------- P3: main fused GEMM + epilogue ----------------
// Per CTA: b, two consecutive i rows -> M = 256 positions (m = il*128 + j), N = 64 (s), K = 128.
// A[m,k]: k<64 -> in[b,i,j,k];  k>=64 -> in[b,j,i,k-64].  B = g_CB.
// Epilogue: + U[b,i,s] + V[b,j,s] + (i==j)*Dg[b,i,s]; leaky-relu; * mask.
#define SA_STRIDE 260   // 4*260 % 32 == 16 -> reduces STS bank conflicts vs 256, keeps 16B alignment

__global__ __launch_bounds__(256, 2) void main_kernel(const float* __restrict__ in,
                                                      const float* __restrict__ mask,
                                                      float* __restrict__ out) {
    int b  = blockIdx.x >> 6;
    int i0 = (blockIdx.x & 63) * 2;
    int tid  = threadIdx.x;
    int sidx = tid & 7;    // -> s = sidx*8 .. +7
    int midx = tid >> 3;   // -> m = midx*8 .. +7

    __shared__ float sA[16][SA_STRIDE];
    __shared__ float sB[16][64];

    float acc[8][8];
#pragma unroll
    for (int r = 0; r < 8; r++)
#pragma unroll
        for (int c = 0; c < 8; c++) acc[r][c] = 0.f;

    const float* Abase = in + (size_t)b * NN * NN * CC;

    for (int kt = 0; kt < 8; kt++) {
        int k0 = kt * 16;
        // load B tile (16 x 64)
        {
            int kk = tid >> 4, sc = (tid & 15) * 4;
            *(float4*)&sB[kk][sc] = *(const float4*)&g_CB[(k0 + kk)*64 + sc];
        }
        // load A tile (256 m x 16 k), transposed into sA[kk][m]
#pragma unroll
        for (int p = 0; p < 4; p++) {
            int q  = tid + p*256;
            int m  = q >> 2;
            int kg = q & 3;
            int k  = k0 + kg*4;
            int i  = i0 + (m >> 7);
            int j  = m & 127;
            const float4* src;
            if (k < 64) src = (const float4*)(Abase + ((size_t)(i*NN + j))*CC + k);
            else        src = (const float4*)(Abase + ((size_t)(j*NN + i))*CC + (k - 64));
            float4 v = *src;
            sA[kg*4+0][m] = v.x;
            sA[kg*4+1][m] = v.y;
            sA[kg*4+2][m] = v.z;
            sA[kg*4+3][m] = v.w;
        }
        __syncthreads();

#pragma unroll
        for (int kk = 0; kk < 16; kk++) {
            float4 a0 = *(const float4*)&sA[kk][midx*8];
            float4 a1 = *(const float4*)&sA[kk][midx*8 + 4];
            float4 b0 = *(const float4*)&sB[kk][sidx*8];
            float4 b1 = *(const float4*)&sB[kk][sidx*8 + 4];
            float av[8] = {a0.x, a0.y, a0.z, a0.w, a1.x, a1.y, a1.z, a1.w};
            float bv[8] = {b0.x, b0.y, b0.z, b0.w, b1.x, b1.y, b1.z, b1.w};
#pragma unroll
            for (int r = 0; r < 8; r++)
#pragma unroll
                for (int c = 0; c < 8; c++) acc[r][c] += av[r] * bv[c];
        }
        __syncthreads();
    }

    // epilogue
    int s0 = sidx * 8;
#pragma unroll
    for (int r = 0; r < 8; r++) {
        int m = midx*8 + r;
        int i = i0 + (m >> 7);
        int j = m & 127;
        int uo = (b*NN + i)*CC + s0;
        int vo = (b*NN + j)*CC + s0;
        float mk = mask[(b*NN + i)*NN + j];
        bool on_diag = (i == j);
        size_t oo = ((size_t)(b*NN + i)*NN + j)*CC + s0;
#pragma unroll
        for (int c = 0; c < 8; c++) {
            float v = acc[r][c] + g_U[uo + c] + g_V[vo + c];
            if (on_diag) v += g_Dg[uo + c];
            v = (v > 0.f) ? v : NEG_SLOPE * v;
            out[oo + c] = v * mk;
        }
    }
}

// ---------------- launch ----------------
extern "C" void kernel_launch(void* const* d_in, const int* in_sizes, int n_in,
                              void* d_out, int out_size) {
    const float* in     = (const float*)d_in[0];
    const float* mask   = (const float*)d_in[1];
    // d_in[2] = nobj (unused: reference hard-codes average_nobj = 49)
    const float* c00    = (const float*)d_in[3];
    const float* c01    = (const float*)d_in[4];
    const float* c10    = (const float*)d_in[5];
    const float* c11    = (const float*)d_in[6];
    const float* bias   = (const float*)d_in[7];
    const float* dbias  = (const float*)d_in[8];
    float* out = (float*)d_out;

    cb_kernel<<<32, 256>>>(c00, c01, c10, c11);
    stats_kernel<<<BB*NN, 256>>>(in);
    trace_kernel<<<BB, 64>>>();
    combine_kernel<<<64, 256>>>(c00, c01, c10, c11, bias, dbias);
    main_kernel<<<BB*64, 256>>>(in, mask, out);
}